// round 9
// baseline (speedup 1.0000x reference)
#include <cuda_runtime.h>
#include <cstdint>

#define T_TOKENS 16384
#define H_DIM    1024
#define M_DIM    512
#define E_NUM    8
#define D_DIM    1024
#define FLAG_CAP 2048

// ---------------------------------------------------------------------------
// Device scratch (tf32-rounded operands stored as f32 bit patterns)
// ---------------------------------------------------------------------------
__device__ float g_h[T_TOKENS * M_DIM];        // router hidden (approx, relu'd)
__device__ int   g_top[T_TOKENS];
__device__ int   g_counts[E_NUM];
__device__ int   g_offsets[E_NUM + 1];
__device__ int   g_cursor[E_NUM];
__device__ int   g_perm[T_TOKENS];
__device__ int   g_nflag;
__device__ int   g_flag[FLAG_CAP];
__device__ float g_Xt[T_TOKENS * H_DIM];       // X, tf32-rounded
__device__ float g_Wt[E_NUM * D_DIM * H_DIM];  // expert_W^T [e][n][k], tf32-rounded
__device__ float g_W1t[M_DIM * H_DIM];         // w1^T [n][k], tf32-rounded

// ---------------------------------------------------------------------------
// Helpers
// ---------------------------------------------------------------------------
__device__ __forceinline__ uint32_t smem_to_u32(const void* p) {
    uint32_t a;
    asm("{ .reg .u64 t; cvta.to.shared.u64 t, %1; cvt.u32.u64 %0, t; }" : "=r"(a) : "l"(p));
    return a;
}
__device__ __forceinline__ float f2tf32(float f) {
    uint32_t u;
    asm("cvt.rna.tf32.f32 %0, %1;" : "=r"(u) : "f"(f));
    return __uint_as_float(u);
}
#define CP_ASYNC16(dst, src) \
    asm volatile("cp.async.cg.shared.global [%0], [%1], 16;" :: "r"(dst), "l"(src))
#define CP_COMMIT()  asm volatile("cp.async.commit_group;" ::: "memory")
#define CP_WAIT1()   asm volatile("cp.async.wait_group 1;" ::: "memory")
#define CP_WAIT0()   asm volatile("cp.async.wait_group 0;" ::: "memory")

__device__ __forceinline__ void mma_tf32(float* c, const uint32_t* a, const uint32_t* b) {
    asm volatile("mma.sync.aligned.m16n8k8.row.col.f32.tf32.tf32.f32 "
                 "{%0,%1,%2,%3}, {%4,%5,%6,%7}, {%8,%9}, {%0,%1,%2,%3};"
                 : "+f"(c[0]), "+f"(c[1]), "+f"(c[2]), "+f"(c[3])
                 : "r"(a[0]), "r"(a[1]), "r"(a[2]), "r"(a[3]), "r"(b[0]), "r"(b[1]));
}

// smem tile geometry: rows of 64 floats padded to 68 (272B, 16B-aligned,
// conflict-free fragment loads: bank = 4*row + col (mod 32))
#define ROW_F   68
#define ROW_B   272
#define MAT_B   (128 * ROW_B)           // 34816 bytes per matrix
#define BUF_B   (2 * MAT_B)             // A + B per stage
#define TILES_OFF 2048
#define SMEM_BYTES (TILES_OFF + 2 * BUF_B)   // 141312

// ---------------------------------------------------------------------------
// K0: zero counters
// ---------------------------------------------------------------------------
__global__ void k_zero() {
    if (threadIdx.x < E_NUM) g_counts[threadIdx.x] = 0;
    if (threadIdx.x == 0) g_nflag = 0;
}

// ---------------------------------------------------------------------------
// Prep: round X to tf32
// ---------------------------------------------------------------------------
__global__ __launch_bounds__(256) void k_round_x(const float* __restrict__ X) {
    const size_t i = ((size_t)blockIdx.x * 256 + threadIdx.x) * 4;
    float4 v = *(const float4*)(X + i);
    v.x = f2tf32(v.x); v.y = f2tf32(v.y); v.z = f2tf32(v.z); v.w = f2tf32(v.w);
    *(float4*)(g_Xt + i) = v;
}

// ---------------------------------------------------------------------------
// Prep: transpose + round expert_W  (W[e][k][n] -> [e][n][k])
// ---------------------------------------------------------------------------
__global__ __launch_bounds__(256) void k_tr_we(const float* __restrict__ W) {
    __shared__ float tile[32][33];
    const int e = blockIdx.z;
    const int kb = blockIdx.x * 32, nb = blockIdx.y * 32;
    const int tx = threadIdx.x & 31, ty = threadIdx.x >> 5;
    const float* Wp = W + ((size_t)e << 20);
#pragma unroll
    for (int i = 0; i < 32; i += 8)
        tile[ty + i][tx] = Wp[(size_t)(kb + ty + i) * D_DIM + nb + tx];
    __syncthreads();
#pragma unroll
    for (int i = 0; i < 32; i += 8)
        g_Wt[((size_t)e << 20) + (size_t)(nb + ty + i) * H_DIM + kb + tx] =
            f2tf32(tile[tx][ty + i]);
}

// ---------------------------------------------------------------------------
// Prep: transpose + round w1  (w1[k][n] -> [n][k])
// ---------------------------------------------------------------------------
__global__ __launch_bounds__(256) void k_tr_w1(const float* __restrict__ W) {
    __shared__ float tile[32][33];
    const int kb = blockIdx.x * 32, nb = blockIdx.y * 32;
    const int tx = threadIdx.x & 31, ty = threadIdx.x >> 5;
#pragma unroll
    for (int i = 0; i < 32; i += 8)
        tile[ty + i][tx] = W[(size_t)(kb + ty + i) * M_DIM + nb + tx];
    __syncthreads();
#pragma unroll
    for (int i = 0; i < 32; i += 8)
        g_W1t[(size_t)(nb + ty + i) * H_DIM + kb + tx] = f2tf32(tile[tx][ty + i]);
}

// ---------------------------------------------------------------------------
// Shared tf32 GEMM mainloop (CTA tile 128x128, KC=64, double-buffered)
// 8 warps = 4(m) x 2(n), warp tile 32x64. A rows given by row pointers.
// ---------------------------------------------------------------------------
struct Frag { float acc[2][8][4]; };

__device__ __forceinline__ void gemm_mainloop(
    char* smem, uint32_t sb, int tid,
    const float* aRowPtr,     // per-thread A source row base (thread's lr row)
    const float* bRowPtr,     // per-thread B source row base
    Frag& fr)
{
    const int lane = tid & 31;
    const int wid = tid >> 5;
    const int warp_m = wid & 3;
    const int warp_n = wid >> 2;
    const int lh = tid & 1;

#pragma unroll
    for (int mi = 0; mi < 2; mi++)
#pragma unroll
        for (int ni = 0; ni < 8; ni++)
#pragma unroll
            for (int j = 0; j < 4; j++) fr.acc[mi][ni][j] = 0.f;

    const int lr = tid >> 1;
    const uint32_t dstA = sb + TILES_OFF + (uint32_t)lr * ROW_B + (uint32_t)lh * 128;
    const uint32_t dstB = dstA + MAT_B;

    auto load_chunk = [&](int c) {
        const uint32_t bufo = (uint32_t)(c & 1) * BUF_B;
        const float* sa = aRowPtr + c * 64 + lh * 32;
        const float* sbp = bRowPtr + c * 64 + lh * 32;
#pragma unroll
        for (int j = 0; j < 8; j++) {
            CP_ASYNC16(dstA + bufo + j * 16, (const char*)sa + j * 16);
            CP_ASYNC16(dstB + bufo + j * 16, (const char*)sbp + j * 16);
        }
    };

    load_chunk(0);
    CP_COMMIT();

    for (int c = 0; c < 16; c++) {
        if (c + 1 < 16) { load_chunk(c + 1); CP_COMMIT(); CP_WAIT1(); }
        else            { CP_WAIT0(); }
        __syncthreads();

        const float* As = (const float*)(smem + TILES_OFF + (c & 1) * BUF_B);
        const float* Bs = As + 128 * ROW_F;
        const int g = lane >> 2, t = lane & 3;
        const float* ap0 = As + (warp_m * 32 + g) * ROW_F + t;
        const float* bp0 = Bs + (warp_n * 64 + g) * ROW_F + t;

#pragma unroll
        for (int ks = 0; ks < 8; ks++) {
            const int c0 = ks * 8;
            uint32_t a[2][4], b[8][2];
#pragma unroll
            for (int mi = 0; mi < 2; mi++) {
                const float* ap = ap0 + mi * 16 * ROW_F;
                a[mi][0] = __float_as_uint(ap[c0]);
                a[mi][1] = __float_as_uint(ap[8 * ROW_F + c0]);
                a[mi][2] = __float_as_uint(ap[c0 + 4]);
                a[mi][3] = __float_as_uint(ap[8 * ROW_F + c0 + 4]);
            }
#pragma unroll
            for (int ni = 0; ni < 8; ni++) {
                const float* bp = bp0 + ni * 8 * ROW_F;
                b[ni][0] = __float_as_uint(bp[c0]);
                b[ni][1] = __float_as_uint(bp[c0 + 4]);
            }
#pragma unroll
            for (int mi = 0; mi < 2; mi++)
#pragma unroll
                for (int ni = 0; ni < 8; ni++)
                    mma_tf32(fr.acc[mi][ni], a[mi], b[ni]);
        }
        __syncthreads();
    }
}

// ---------------------------------------------------------------------------
// K1: router hidden: g_h = relu(Xt @ W1t^T + b1)
// ---------------------------------------------------------------------------
__global__ __launch_bounds__(256) void k_gemm1_tf32(const float* __restrict__ b1) {
    extern __shared__ char smem[];
    const uint32_t sb = smem_to_u32(smem);
    const int tid = threadIdx.x;
    const int lane = tid & 31;
    const int wid = tid >> 5;
    const int warp_m = wid & 3;
    const int warp_n = wid >> 2;
    const int rowBase = blockIdx.x * 128;
    const int colBase = blockIdx.y * 128;

    float* s_bias = (float*)(smem + 576);
    if (tid < 128) s_bias[tid] = b1[colBase + tid];
    __syncthreads();

    const int lr = tid >> 1;
    const float* aRow = g_Xt + (size_t)(rowBase + lr) * H_DIM;
    const float* bRow = g_W1t + (size_t)(colBase + lr) * H_DIM;

    Frag fr;
    gemm_mainloop(smem, sb, tid, aRow, bRow, fr);

#pragma unroll
    for (int mi = 0; mi < 2; mi++) {
        const int r0 = rowBase + warp_m * 32 + mi * 16 + (lane >> 2);
        const int r1 = r0 + 8;
#pragma unroll
        for (int ni = 0; ni < 8; ni++) {
            const int col = warp_n * 64 + ni * 8 + (lane & 3) * 2;
            float2 w0{fr.acc[mi][ni][0] + s_bias[col], fr.acc[mi][ni][1] + s_bias[col + 1]};
            float2 w1v{fr.acc[mi][ni][2] + s_bias[col], fr.acc[mi][ni][3] + s_bias[col + 1]};
            w0.x = w0.x > 0.f ? w0.x : 0.f;  w0.y = w0.y > 0.f ? w0.y : 0.f;
            w1v.x = w1v.x > 0.f ? w1v.x : 0.f; w1v.y = w1v.y > 0.f ? w1v.y : 0.f;
            *(float2*)(g_h + (size_t)r0 * M_DIM + colBase + col) = w0;
            *(float2*)(g_h + (size_t)r1 * M_DIM + colBase + col) = w1v;
        }
    }
}

// ---------------------------------------------------------------------------
// K2: routing scores + argmax + histogram; flag gap < 8e-3 for exact recheck
// ---------------------------------------------------------------------------
__global__ __launch_bounds__(256) void k_route(const float* __restrict__ w2,
                                               const float* __restrict__ b2) {
    __shared__ float s_w2[M_DIM * E_NUM];
    for (int i = threadIdx.x; i < M_DIM * E_NUM; i += 256) s_w2[i] = w2[i];
    __syncthreads();

    const int warp = threadIdx.x >> 5, lane = threadIdx.x & 31;
    const int t = blockIdx.x * 8 + warp;
    float acc[E_NUM] = {};
    const float* hrow = &g_h[(size_t)t * M_DIM];
    for (int m = lane; m < M_DIM; m += 32) {
        const float hv = hrow[m];
#pragma unroll
        for (int e = 0; e < E_NUM; e++) acc[e] += hv * s_w2[m * E_NUM + e];
    }
#pragma unroll
    for (int e = 0; e < E_NUM; e++) {
        float v = acc[e];
#pragma unroll
        for (int off = 16; off > 0; off >>= 1) v += __shfl_down_sync(0xffffffffu, v, off);
        acc[e] = v;
    }
    if (lane == 0) {
        float best = acc[0] + b2[0], second = -1e30f;
        int bi = 0;
#pragma unroll
        for (int e = 1; e < E_NUM; e++) {
            const float v = acc[e] + b2[e];
            if (v > best) { second = best; best = v; bi = e; }
            else if (v > second) { second = v; }
        }
        g_top[t] = bi;
        atomicAdd(&g_counts[bi], 1);
        if (best - second < 8e-3f) {
            const int pos = atomicAdd(&g_nflag, 1);
            if (pos < FLAG_CAP) g_flag[pos] = t;
        }
    }
}

// ---------------------------------------------------------------------------
// K2b: exact fp32 recompute for flagged tokens (4 tokens per block, shared
//      w1 row reads, fully deterministic reductions). Patch g_top / g_counts.
// ---------------------------------------------------------------------------
__global__ __launch_bounds__(256) void k_fix(const float* __restrict__ X,
                                             const float* __restrict__ w1,
                                             const float* __restrict__ b1,
                                             const float* __restrict__ w2,
                                             const float* __restrict__ b2) {
    const int nf = g_nflag < FLAG_CAP ? g_nflag : FLAG_CAP;
    const int base = blockIdx.x * 4;
    if (base >= nf) return;
    const int ntok = (nf - base) < 4 ? (nf - base) : 4;

    __shared__ float x_s[4][H_DIM];      // 16 KB
    __shared__ float h_s[4][M_DIM];      // 8 KB
    __shared__ float ss[4][E_NUM];
    const int tid = threadIdx.x;

    for (int t = 0; t < ntok; t++) {
        const float* x = X + (size_t)g_flag[base + t] * H_DIM;
        for (int k = tid; k < H_DIM; k += 256) x_s[t][k] = x[k];
    }
    __syncthreads();

    // each thread owns m-columns tid and tid+256
    float acc[2][4] = {};
    for (int k = 0; k < H_DIM; k++) {
        const float w0 = w1[(size_t)k * M_DIM + tid];
        const float w1v = w1[(size_t)k * M_DIM + tid + 256];
#pragma unroll
        for (int t = 0; t < 4; t++) {
            const float xv = x_s[t][k];
            acc[0][t] += w0 * xv;
            acc[1][t] += w1v * xv;
        }
    }
#pragma unroll
    for (int i = 0; i < 2; i++) {
        const int m = tid + i * 256;
        const float bb = b1[m];
#pragma unroll
        for (int t = 0; t < 4; t++) {
            const float v = acc[i][t] + bb;
            h_s[t][m] = v > 0.f ? v : 0.f;
        }
    }
    __syncthreads();

    // deterministic serial score reduction: one thread per (t, e)
    if (tid < 4 * E_NUM) {
        const int t = tid >> 3, e = tid & 7;
        float s = 0.f;
        for (int m = 0; m < M_DIM; m++) s += h_s[t][m] * w2[m * E_NUM + e];
        ss[t][e] = s + b2[e];
    }
    __syncthreads();

    if (tid < 4 && tid < ntok) {
        float best = ss[tid][0];
        int bi = 0;
#pragma unroll
        for (int e = 1; e < E_NUM; e++)
            if (ss[tid][e] > best) { best = ss[tid][e]; bi = e; }
        const int tok = g_flag[base + tid];
        const int old = g_top[tok];
        if (bi != old) {
            g_top[tok] = bi;
            atomicSub(&g_counts[old], 1);
            atomicAdd(&g_counts[bi], 1);
        }
    }
}

__global__ void k_scan() {
    if (threadIdx.x == 0) {
        int off = 0;
        for (int e = 0; e < E_NUM; e++) {
            g_offsets[e] = off;
            g_cursor[e]  = off;
            off += g_counts[e];
        }
        g_offsets[E_NUM] = off;
    }
}

__global__ void k_scatter() {
    const int t = blockIdx.x * blockDim.x + threadIdx.x;
    if (t < T_TOKENS) {
        const int e = g_top[t];
        const int pos = atomicAdd(&g_cursor[e], 1);
        g_perm[pos] = t;
    }
}

// ---------------------------------------------------------------------------
// K5: expert GEMM (tf32, gathered token rows)
// ---------------------------------------------------------------------------
__global__ __launch_bounds__(256) void k_expert_tf32(float* __restrict__ out,
                                                     const float* __restrict__ eb) {
    const int e = blockIdx.z;
    const int off = g_offsets[e];
    const int n = g_offsets[e + 1] - off;
    const int rowBase = blockIdx.x * 128;
    if (rowBase >= n) return;

    extern __shared__ char smem[];
    const uint32_t sb = smem_to_u32(smem);
    const int tid = threadIdx.x;
    const int lane = tid & 31;
    const int wid = tid >> 5;
    const int warp_m = wid & 3;
    const int warp_n = wid >> 2;
    const int colBase = blockIdx.y * 128;

    int*   s_tok  = (int*)(smem + 64);
    float* s_bias = (float*)(smem + 576);
    if (tid < 128) {
        const int m = rowBase + tid;
        s_tok[tid]  = g_perm[off + (m < n ? m : 0)];
        s_bias[tid] = eb[(size_t)e * D_DIM + colBase + tid];
    }
    __syncthreads();

    const int lr = tid >> 1;
    const float* aRow = g_Xt + (size_t)s_tok[lr] * H_DIM;
    const float* bRow = g_Wt + ((size_t)e << 20) + (size_t)(colBase + lr) * H_DIM;

    Frag fr;
    gemm_mainloop(smem, sb, tid, aRow, bRow, fr);

#pragma unroll
    for (int mi = 0; mi < 2; mi++) {
        const int r0 = warp_m * 32 + mi * 16 + (lane >> 2);
        const int r1 = r0 + 8;
        const bool v0 = (rowBase + r0) < n;
        const bool v1 = (rowBase + r1) < n;
        float* o0 = out + (size_t)s_tok[r0] * D_DIM + colBase;
        float* o1 = out + (size_t)s_tok[r1] * D_DIM + colBase;
#pragma unroll
        for (int ni = 0; ni < 8; ni++) {
            const int col = warp_n * 64 + ni * 8 + (lane & 3) * 2;
            if (v0) {
                float2 w{fr.acc[mi][ni][0] + s_bias[col], fr.acc[mi][ni][1] + s_bias[col + 1]};
                *(float2*)(o0 + col) = w;
            }
            if (v1) {
                float2 w{fr.acc[mi][ni][2] + s_bias[col], fr.acc[mi][ni][3] + s_bias[col + 1]};
                *(float2*)(o1 + col) = w;
            }
        }
    }
}

// ---------------------------------------------------------------------------
// Launch
// ---------------------------------------------------------------------------
extern "C" void kernel_launch(void* const* d_in, const int* in_sizes, int n_in,
                              void* d_out, int out_size) {
    const float* X  = (const float*)d_in[0];
    const float* w1 = (const float*)d_in[1];
    const float* b1 = (const float*)d_in[2];
    const float* w2 = (const float*)d_in[3];
    const float* b2 = (const float*)d_in[4];
    const float* eW = (const float*)d_in[5];
    const float* eb = (const float*)d_in[6];
    float* out = (float*)d_out;

    static bool attr_set = false;
    if (!attr_set) {
        cudaFuncSetAttribute(k_expert_tf32, cudaFuncAttributeMaxDynamicSharedMemorySize,
                             SMEM_BYTES);
        cudaFuncSetAttribute(k_gemm1_tf32, cudaFuncAttributeMaxDynamicSharedMemorySize,
                             SMEM_BYTES);
        attr_set = true;
    }

    k_zero<<<1, 32>>>();
    k_round_x<<<(T_TOKENS * H_DIM) / (256 * 4), 256>>>(X);
    k_tr_w1<<<dim3(H_DIM / 32, M_DIM / 32), 256>>>(w1);
    k_tr_we<<<dim3(H_DIM / 32, D_DIM / 32, E_NUM), 256>>>(eW);
    k_gemm1_tf32<<<dim3(T_TOKENS / 128, M_DIM / 128), 256, SMEM_BYTES>>>(b1);
    k_route<<<T_TOKENS / 8, 256>>>(w2, b2);
    k_fix<<<FLAG_CAP / 4, 256>>>(X, w1, b1, w2, b2);
    k_scan<<<1, 1>>>();
    k_scatter<<<T_TOKENS / 256, 256>>>();
    k_expert_tf32<<<dim3(T_TOKENS / 128, D_DIM / 128, E_NUM), 256, SMEM_BYTES>>>(out, eb);
}

// round 10
// speedup vs baseline: 2.9827x; 2.9827x over previous
#include <cuda_runtime.h>
#include <cuda_fp16.h>
#include <cstdint>

#define T_TOKENS 16384
#define H_DIM    1024
#define M_DIM    512
#define E_NUM    8
#define D_DIM    1024
#define FLAG_CAP 2048

// ---------------------------------------------------------------------------
// Device scratch
// ---------------------------------------------------------------------------
__device__ float g_h[T_TOKENS * M_DIM];        // router hidden (approx, relu'd)
__device__ int   g_top[T_TOKENS];
__device__ int   g_counts[E_NUM];
__device__ int   g_offsets[E_NUM + 1];
__device__ int   g_cursor[E_NUM];
__device__ int   g_perm[T_TOKENS];
__device__ int   g_nflag;
__device__ int   g_flag[FLAG_CAP];
__device__ __half g_Xh[T_TOKENS * H_DIM];      // X, fp16
__device__ __half g_Wh[E_NUM * D_DIM * H_DIM]; // expert_W^T [e][n][k], fp16
__device__ __half g_W1h[M_DIM * H_DIM];        // w1^T [n][k], fp16

// ---------------------------------------------------------------------------
// Helpers (base-feature PTX: cp.async, ldmatrix, mma.sync)
// ---------------------------------------------------------------------------
__device__ __forceinline__ uint32_t smem_to_u32(const void* p) {
    uint32_t a;
    asm("{ .reg .u64 t; cvta.to.shared.u64 t, %1; cvt.u32.u64 %0, t; }" : "=r"(a) : "l"(p));
    return a;
}
#define SW128(o) ((o) ^ (((o) >> 3) & 0x70))

#define CP_ASYNC16(dst, src) \
    asm volatile("cp.async.cg.shared.global [%0], [%1], 16;" :: "r"(dst), "l"(src))
#define CP_COMMIT()  asm volatile("cp.async.commit_group;" ::: "memory")
#define CP_WAIT1()   asm volatile("cp.async.wait_group 1;" ::: "memory")
#define CP_WAIT0()   asm volatile("cp.async.wait_group 0;" ::: "memory")

__device__ __forceinline__ void ldsm4(uint32_t* r, uint32_t addr) {
    asm volatile("ldmatrix.sync.aligned.m8n8.x4.shared.b16 {%0,%1,%2,%3}, [%4];"
                 : "=r"(r[0]), "=r"(r[1]), "=r"(r[2]), "=r"(r[3]) : "r"(addr));
}
__device__ __forceinline__ void mma_f16(float* c, const uint32_t* a, const uint32_t* b) {
    asm volatile("mma.sync.aligned.m16n8k16.row.col.f32.f16.f16.f32 "
                 "{%0,%1,%2,%3}, {%4,%5,%6,%7}, {%8,%9}, {%0,%1,%2,%3};"
                 : "+f"(c[0]), "+f"(c[1]), "+f"(c[2]), "+f"(c[3])
                 : "r"(a[0]), "r"(a[1]), "r"(a[2]), "r"(a[3]), "r"(b[0]), "r"(b[1]));
}

// smem: [64] s_tok 512B, [576] s_bias 512B, [2048] 2 stages x (A 16K | B 16K)
#define TILES_OFF 2048
#define STAGE_B   32768
#define SMEM_BYTES (TILES_OFF + 2 * STAGE_B)   // 67584

// ---------------------------------------------------------------------------
// K0: zero counters
// ---------------------------------------------------------------------------
__global__ void k_zero() {
    if (threadIdx.x < E_NUM) g_counts[threadIdx.x] = 0;
    if (threadIdx.x == 0) g_nflag = 0;
}

// ---------------------------------------------------------------------------
// Prep: convert X to fp16
// ---------------------------------------------------------------------------
__global__ __launch_bounds__(256) void k_cvt_x(const float* __restrict__ X) {
    const size_t i = ((size_t)blockIdx.x * 256 + threadIdx.x) * 4;
    float4 v = *(const float4*)(X + i);
    __half2 h0 = __floats2half2_rn(v.x, v.y);
    __half2 h1 = __floats2half2_rn(v.z, v.w);
    *(__half2*)(g_Xh + i)     = h0;
    *(__half2*)(g_Xh + i + 2) = h1;
}

// ---------------------------------------------------------------------------
// Prep: transpose + convert expert_W  (W[e][k][n] -> [e][n][k], fp16)
// ---------------------------------------------------------------------------
__global__ __launch_bounds__(256) void k_tr_we(const float* __restrict__ W) {
    __shared__ float tile[32][33];
    const int e = blockIdx.z;
    const int kb = blockIdx.x * 32, nb = blockIdx.y * 32;
    const int tx = threadIdx.x & 31, ty = threadIdx.x >> 5;
    const float* Wp = W + ((size_t)e << 20);
#pragma unroll
    for (int i = 0; i < 32; i += 8)
        tile[ty + i][tx] = Wp[(size_t)(kb + ty + i) * D_DIM + nb + tx];
    __syncthreads();
#pragma unroll
    for (int i = 0; i < 32; i += 8)
        g_Wh[((size_t)e << 20) + (size_t)(nb + ty + i) * H_DIM + kb + tx] =
            __float2half_rn(tile[tx][ty + i]);
}

// ---------------------------------------------------------------------------
// Prep: transpose + convert w1  (w1[k][n] -> [n][k], fp16)
// ---------------------------------------------------------------------------
__global__ __launch_bounds__(256) void k_tr_w1(const float* __restrict__ W) {
    __shared__ float tile[32][33];
    const int kb = blockIdx.x * 32, nb = blockIdx.y * 32;
    const int tx = threadIdx.x & 31, ty = threadIdx.x >> 5;
#pragma unroll
    for (int i = 0; i < 32; i += 8)
        tile[ty + i][tx] = W[(size_t)(kb + ty + i) * M_DIM + nb + tx];
    __syncthreads();
#pragma unroll
    for (int i = 0; i < 32; i += 8)
        g_W1h[(size_t)(nb + ty + i) * H_DIM + kb + tx] = __float2half_rn(tile[tx][ty + i]);
}

// ---------------------------------------------------------------------------
// Shared fp16 GEMM mainloop: CTA 128x128, KC=64, double-buffered cp.async,
// SW128 smem rows (128B). 8 warps = 4(m) x 2(n), warp tile 32x64.
// ---------------------------------------------------------------------------
struct Frag { float acc[2][8][4]; };

__device__ __forceinline__ void gemm_mainloop(
    uint32_t sb, int tid, const __half* aRow, const __half* bRow, Frag& fr)
{
    const int lane = tid & 31;
    const int wid = tid >> 5;
    const int warp_m = wid & 3;
    const int warp_n = wid >> 2;
    const int lr = tid >> 1;
    const int lh = tid & 1;

#pragma unroll
    for (int mi = 0; mi < 2; mi++)
#pragma unroll
        for (int ni = 0; ni < 8; ni++)
#pragma unroll
            for (int j = 0; j < 4; j++) fr.acc[mi][ni][j] = 0.f;

    auto load_chunk = [&](int c) {
        const uint32_t tb = sb + TILES_OFF + (uint32_t)(c & 1) * STAGE_B;
        const int kElem = c * 64;
#pragma unroll
        for (int j = 0; j < 4; j++) {
            const uint32_t o = SW128((uint32_t)(lr * 128 + lh * 64 + j * 16));
            CP_ASYNC16(tb + o,         (const char*)(aRow + kElem) + j * 16);
            CP_ASYNC16(tb + 16384 + o, (const char*)(bRow + kElem) + j * 16);
        }
    };

    load_chunk(0);
    CP_COMMIT();

    for (int c = 0; c < 16; c++) {
        if (c + 1 < 16) { load_chunk(c + 1); CP_COMMIT(); CP_WAIT1(); }
        else            { CP_WAIT0(); }
        __syncthreads();

        const uint32_t tb = sb + TILES_OFF + (uint32_t)(c & 1) * STAGE_B;
#pragma unroll
        for (int ks = 0; ks < 4; ks++) {
            uint32_t aF[2][4];
#pragma unroll
            for (int mi = 0; mi < 2; mi++) {
                const int row = warp_m * 32 + mi * 16 + (lane & 15);
                const uint32_t o =
                    (uint32_t)(row * 128 + ((ks * 32 + (lane >> 4) * 16) ^ ((row & 7) << 4)));
                ldsm4(aF[mi], tb + o);
            }
            uint32_t bF[8][2];
#pragma unroll
            for (int nt = 0; nt < 4; nt++) {
                const int row = warp_n * 64 + nt * 16 + ((lane >> 4) << 3) + (lane & 7);
                const uint32_t o =
                    (uint32_t)(row * 128 +
                               ((ks * 32 + ((lane >> 3) & 1) * 16) ^ ((row & 7) << 4)));
                uint32_t r4[4];
                ldsm4(r4, tb + 16384 + o);
                bF[nt * 2][0] = r4[0]; bF[nt * 2][1] = r4[1];
                bF[nt * 2 + 1][0] = r4[2]; bF[nt * 2 + 1][1] = r4[3];
            }
#pragma unroll
            for (int mi = 0; mi < 2; mi++)
#pragma unroll
                for (int ni = 0; ni < 8; ni++)
                    mma_f16(fr.acc[mi][ni], aF[mi], bF[ni]);
        }
        __syncthreads();
    }
}

// ---------------------------------------------------------------------------
// K1: router hidden: g_h = relu(Xh @ W1h^T + b1)   (fp16 HMMA)
// ---------------------------------------------------------------------------
__global__ __launch_bounds__(256) void k_gemm1_f16(const float* __restrict__ b1) {
    extern __shared__ char smem[];
    const uint32_t sb = smem_to_u32(smem);
    const int tid = threadIdx.x;
    const int lane = tid & 31;
    const int wid = tid >> 5;
    const int warp_m = wid & 3;
    const int warp_n = wid >> 2;
    const int rowBase = blockIdx.x * 128;
    const int colBase = blockIdx.y * 128;

    float* s_bias = (float*)(smem + 576);
    if (tid < 128) s_bias[tid] = b1[colBase + tid];
    __syncthreads();

    const int lr = tid >> 1;
    const int lh = tid & 1;
    const __half* aRow = g_Xh + (size_t)(rowBase + lr) * H_DIM + lh * 32;
    const __half* bRow = g_W1h + (size_t)(colBase + lr) * H_DIM + lh * 32;

    Frag fr;
    gemm_mainloop(sb, tid, aRow, bRow, fr);

#pragma unroll
    for (int mi = 0; mi < 2; mi++) {
        const int r0 = rowBase + warp_m * 32 + mi * 16 + (lane >> 2);
        const int r1 = r0 + 8;
#pragma unroll
        for (int ni = 0; ni < 8; ni++) {
            const int col = warp_n * 64 + ni * 8 + (lane & 3) * 2;
            float2 w0{fr.acc[mi][ni][0] + s_bias[col], fr.acc[mi][ni][1] + s_bias[col + 1]};
            float2 w1v{fr.acc[mi][ni][2] + s_bias[col], fr.acc[mi][ni][3] + s_bias[col + 1]};
            w0.x = w0.x > 0.f ? w0.x : 0.f;  w0.y = w0.y > 0.f ? w0.y : 0.f;
            w1v.x = w1v.x > 0.f ? w1v.x : 0.f; w1v.y = w1v.y > 0.f ? w1v.y : 0.f;
            *(float2*)(g_h + (size_t)r0 * M_DIM + colBase + col) = w0;
            *(float2*)(g_h + (size_t)r1 * M_DIM + colBase + col) = w1v;
        }
    }
}

// ---------------------------------------------------------------------------
// K2: routing scores + argmax + histogram; flag gap < 8e-3
// ---------------------------------------------------------------------------
__global__ __launch_bounds__(256) void k_route(const float* __restrict__ w2,
                                               const float* __restrict__ b2) {
    __shared__ float s_w2[M_DIM * E_NUM];
    for (int i = threadIdx.x; i < M_DIM * E_NUM; i += 256) s_w2[i] = w2[i];
    __syncthreads();

    const int warp = threadIdx.x >> 5, lane = threadIdx.x & 31;
    const int t = blockIdx.x * 8 + warp;
    float acc[E_NUM] = {};
    const float* hrow = &g_h[(size_t)t * M_DIM];
    for (int m = lane; m < M_DIM; m += 32) {
        const float hv = hrow[m];
#pragma unroll
        for (int e = 0; e < E_NUM; e++) acc[e] += hv * s_w2[m * E_NUM + e];
    }
#pragma unroll
    for (int e = 0; e < E_NUM; e++) {
        float v = acc[e];
#pragma unroll
        for (int off = 16; off > 0; off >>= 1) v += __shfl_down_sync(0xffffffffu, v, off);
        acc[e] = v;
    }
    if (lane == 0) {
        float best = acc[0] + b2[0], second = -1e30f;
        int bi = 0;
#pragma unroll
        for (int e = 1; e < E_NUM; e++) {
            const float v = acc[e] + b2[e];
            if (v > best) { second = best; best = v; bi = e; }
            else if (v > second) { second = v; }
        }
        g_top[t] = bi;
        atomicAdd(&g_counts[bi], 1);
        if (best - second < 8e-3f) {
            const int pos = atomicAdd(&g_nflag, 1);
            if (pos < FLAG_CAP) g_flag[pos] = t;
        }
    }
}

// ---------------------------------------------------------------------------
// K2b: exact fp32 recompute for flagged tokens (deterministic), patch routing
// ---------------------------------------------------------------------------
__global__ __launch_bounds__(256) void k_fix(const float* __restrict__ X,
                                             const float* __restrict__ w1,
                                             const float* __restrict__ b1,
                                             const float* __restrict__ w2,
                                             const float* __restrict__ b2) {
    const int nf = g_nflag < FLAG_CAP ? g_nflag : FLAG_CAP;
    const int base = blockIdx.x * 4;
    if (base >= nf) return;
    const int ntok = (nf - base) < 4 ? (nf - base) : 4;

    __shared__ float x_s[4][H_DIM];
    __shared__ float h_s[4][M_DIM];
    __shared__ float ss[4][E_NUM];
    const int tid = threadIdx.x;

    for (int t = 0; t < ntok; t++) {
        const float* x = X + (size_t)g_flag[base + t] * H_DIM;
        for (int k = tid; k < H_DIM; k += 256) x_s[t][k] = x[k];
    }
    __syncthreads();

    float acc[2][4] = {};
    for (int k = 0; k < H_DIM; k++) {
        const float w0 = w1[(size_t)k * M_DIM + tid];
        const float w1v = w1[(size_t)k * M_DIM + tid + 256];
#pragma unroll
        for (int t = 0; t < 4; t++) {
            const float xv = x_s[t][k];
            acc[0][t] += w0 * xv;
            acc[1][t] += w1v * xv;
        }
    }
#pragma unroll
    for (int i = 0; i < 2; i++) {
        const int m = tid + i * 256;
        const float bb = b1[m];
#pragma unroll
        for (int t = 0; t < 4; t++) {
            const float v = acc[i][t] + bb;
            h_s[t][m] = v > 0.f ? v : 0.f;
        }
    }
    __syncthreads();

    if (tid < 4 * E_NUM) {
        const int t = tid >> 3, e = tid & 7;
        float s = 0.f;
        for (int m = 0; m < M_DIM; m++) s += h_s[t][m] * w2[m * E_NUM + e];
        ss[t][e] = s + b2[e];
    }
    __syncthreads();

    if (tid < 4 && tid < ntok) {
        float best = ss[tid][0];
        int bi = 0;
#pragma unroll
        for (int e = 1; e < E_NUM; e++)
            if (ss[tid][e] > best) { best = ss[tid][e]; bi = e; }
        const int tok = g_flag[base + tid];
        const int old = g_top[tok];
        if (bi != old) {
            g_top[tok] = bi;
            atomicSub(&g_counts[old], 1);
            atomicAdd(&g_counts[bi], 1);
        }
    }
}

__global__ void k_scan() {
    if (threadIdx.x == 0) {
        int off = 0;
        for (int e = 0; e < E_NUM; e++) {
            g_offsets[e] = off;
            g_cursor[e]  = off;
            off += g_counts[e];
        }
        g_offsets[E_NUM] = off;
    }
}

__global__ void k_scatter() {
    const int t = blockIdx.x * blockDim.x + threadIdx.x;
    if (t < T_TOKENS) {
        const int e = g_top[t];
        const int pos = atomicAdd(&g_cursor[e], 1);
        g_perm[pos] = t;
    }
}

// ---------------------------------------------------------------------------
// K5: expert GEMM (fp16 HMMA, gathered token rows)
// ---------------------------------------------------------------------------
__global__ __launch_bounds__(256) void k_expert_f16(float* __restrict__ out,
                                                    const float* __restrict__ eb) {
    const int e = blockIdx.z;
    const int off = g_offsets[e];
    const int n = g_offsets[e + 1] - off;
    const int rowBase = blockIdx.x * 128;
    if (rowBase >= n) return;

    extern __shared__ char smem[];
    const uint32_t sb = smem_to_u32(smem);
    const int tid = threadIdx.x;
    const int lane = tid & 31;
    const int wid = tid >> 5;
    const int warp_m = wid & 3;
    const int warp_n = wid >> 2;
    const int colBase = blockIdx.y * 128;

    int*   s_tok  = (int*)(smem + 64);
    float* s_bias = (float*)(smem + 576);
    if (tid < 128) {
        const int m = rowBase + tid;
        s_tok[tid]  = g_perm[off + (m < n ? m : 0)];
        s_bias[tid] = eb[(size_t)e * D_DIM + colBase + tid];
    }
    __syncthreads();

    const int lr = tid >> 1;
    const int lh = tid & 1;
    const __half* aRow = g_Xh + (size_t)s_tok[lr] * H_DIM + lh * 32;
    const __half* bRow = g_Wh + ((size_t)e << 20) + (size_t)(colBase + lr) * H_DIM + lh * 32;

    Frag fr;
    gemm_mainloop(sb, tid, aRow, bRow, fr);

#pragma unroll
    for (int mi = 0; mi < 2; mi++) {
        const int r0 = warp_m * 32 + mi * 16 + (lane >> 2);
        const int r1 = r0 + 8;
        const bool v0 = (rowBase + r0) < n;
        const bool v1 = (rowBase + r1) < n;
        float* o0 = out + (size_t)s_tok[r0] * D_DIM + colBase;
        float* o1 = out + (size_t)s_tok[r1] * D_DIM + colBase;
#pragma unroll
        for (int ni = 0; ni < 8; ni++) {
            const int col = warp_n * 64 + ni * 8 + (lane & 3) * 2;
            if (v0) {
                float2 w{fr.acc[mi][ni][0] + s_bias[col], fr.acc[mi][ni][1] + s_bias[col + 1]};
                *(float2*)(o0 + col) = w;
            }
            if (v1) {
                float2 w{fr.acc[mi][ni][2] + s_bias[col], fr.acc[mi][ni][3] + s_bias[col + 1]};
                *(float2*)(o1 + col) = w;
            }
        }
    }
}

// ---------------------------------------------------------------------------
// Launch
// ---------------------------------------------------------------------------
extern "C" void kernel_launch(void* const* d_in, const int* in_sizes, int n_in,
                              void* d_out, int out_size) {
    const float* X  = (const float*)d_in[0];
    const float* w1 = (const float*)d_in[1];
    const float* b1 = (const float*)d_in[2];
    const float* w2 = (const float*)d_in[3];
    const float* b2 = (const float*)d_in[4];
    const float* eW = (const float*)d_in[5];
    const float* eb = (const float*)d_in[6];
    float* out = (float*)d_out;

    static bool attr_set = false;
    if (!attr_set) {
        cudaFuncSetAttribute(k_expert_f16, cudaFuncAttributeMaxDynamicSharedMemorySize,
                             SMEM_BYTES);
        cudaFuncSetAttribute(k_gemm1_f16, cudaFuncAttributeMaxDynamicSharedMemorySize,
                             SMEM_BYTES);
        attr_set = true;
    }

    k_zero<<<1, 32>>>();
    k_cvt_x<<<(T_TOKENS * H_DIM) / (256 * 4), 256>>>(X);
    k_tr_w1<<<dim3(H_DIM / 32, M_DIM / 32), 256>>>(w1);
    k_tr_we<<<dim3(H_DIM / 32, D_DIM / 32, E_NUM), 256>>>(eW);
    k_gemm1_f16<<<dim3(T_TOKENS / 128, M_DIM / 128), 256, SMEM_BYTES>>>(b1);
    k_route<<<T_TOKENS / 8, 256>>>(w2, b2);
    k_fix<<<FLAG_CAP / 4, 256>>>(X, w1, b1, w2, b2);
    k_scan<<<1, 1>>>();
    k_scatter<<<T_TOKENS / 256, 256>>>();
    k_expert_f16<<<dim3(T_TOKENS / 128, D_DIM / 128, E_NUM), 256, SMEM_BYTES>>>(out, eb);
}

// round 13
// speedup vs baseline: 3.1943x; 1.0710x over previous
#include <cuda_runtime.h>
#include <cuda_fp16.h>
#include <cstdint>

#define T_TOKENS 16384
#define H_DIM    1024
#define M_DIM    512
#define E_NUM    8
#define D_DIM    1024
#define FLAG_CAP 2048

// ---------------------------------------------------------------------------
// Device scratch
// ---------------------------------------------------------------------------
__device__ float g_part[8 * T_TOKENS * E_NUM];  // per-col-slice partial scores
__device__ int   g_top[T_TOKENS];
__device__ int   g_counts[E_NUM];
__device__ int   g_offsets[E_NUM + 1];
__device__ int   g_cursor[E_NUM];
__device__ int   g_perm[T_TOKENS];
__device__ int   g_nflag;
__device__ int   g_flag[FLAG_CAP];
__device__ __half g_Xh[T_TOKENS * H_DIM];      // X, fp16
__device__ __half g_Wh[E_NUM * D_DIM * H_DIM]; // expert_W^T [e][n][k], fp16
__device__ __half g_W1h[M_DIM * H_DIM];        // w1^T [n][k], fp16

// ---------------------------------------------------------------------------
// Helpers (base-feature PTX: cp.async, ldmatrix, mma.sync)
// ---------------------------------------------------------------------------
__device__ __forceinline__ uint32_t smem_to_u32(const void* p) {
    uint32_t a;
    asm("{ .reg .u64 t; cvta.to.shared.u64 t, %1; cvt.u32.u64 %0, t; }" : "=r"(a) : "l"(p));
    return a;
}
#define SW128(o) ((o) ^ (((o) >> 3) & 0x70))

#define CP_ASYNC16(dst, src) \
    asm volatile("cp.async.cg.shared.global [%0], [%1], 16;" :: "r"(dst), "l"(src))
#define CP_COMMIT()  asm volatile("cp.async.commit_group;" ::: "memory")
#define CP_WAIT1()   asm volatile("cp.async.wait_group 1;" ::: "memory")
#define CP_WAIT0()   asm volatile("cp.async.wait_group 0;" ::: "memory")

__device__ __forceinline__ void ldsm4(uint32_t* r, uint32_t addr) {
    asm volatile("ldmatrix.sync.aligned.m8n8.x4.shared.b16 {%0,%1,%2,%3}, [%4];"
                 : "=r"(r[0]), "=r"(r[1]), "=r"(r[2]), "=r"(r[3]) : "r"(addr));
}
__device__ __forceinline__ void mma_f16(float* c, const uint32_t* a, const uint32_t* b) {
    asm volatile("mma.sync.aligned.m16n8k16.row.col.f32.f16.f16.f32 "
                 "{%0,%1,%2,%3}, {%4,%5,%6,%7}, {%8,%9}, {%0,%1,%2,%3};"
                 : "+f"(c[0]), "+f"(c[1]), "+f"(c[2]), "+f"(c[3])
                 : "r"(a[0]), "r"(a[1]), "r"(a[2]), "r"(a[3]), "r"(b[0]), "r"(b[1]));
}

// smem: [64] s_tok 512B, [576] s_bias 512B, [2048] 2 stages x (A 16K | B 16K)
#define TILES_OFF 2048
#define STAGE_B   32768
#define SMEM_BYTES (TILES_OFF + 2 * STAGE_B)   // 67584

// ---------------------------------------------------------------------------
// K0: zero counters
// ---------------------------------------------------------------------------
__global__ void k_zero() {
    if (threadIdx.x < E_NUM) g_counts[threadIdx.x] = 0;
    if (threadIdx.x == 0) g_nflag = 0;
}

// ---------------------------------------------------------------------------
// Prep: convert X to fp16
// ---------------------------------------------------------------------------
__global__ __launch_bounds__(256) void k_cvt_x(const float* __restrict__ X) {
    const size_t i = ((size_t)blockIdx.x * 256 + threadIdx.x) * 4;
    float4 v = *(const float4*)(X + i);
    *(__half2*)(g_Xh + i)     = __floats2half2_rn(v.x, v.y);
    *(__half2*)(g_Xh + i + 2) = __floats2half2_rn(v.z, v.w);
}

// ---------------------------------------------------------------------------
// Prep: transpose + convert expert_W  (W[e][k][n] -> [e][n][k], fp16)
// ---------------------------------------------------------------------------
__global__ __launch_bounds__(256) void k_tr_we(const float* __restrict__ W) {
    __shared__ float tile[32][33];
    const int e = blockIdx.z;
    const int kb = blockIdx.x * 32, nb = blockIdx.y * 32;
    const int tx = threadIdx.x & 31, ty = threadIdx.x >> 5;
    const float* Wp = W + ((size_t)e << 20);
#pragma unroll
    for (int i = 0; i < 32; i += 8)
        tile[ty + i][tx] = Wp[(size_t)(kb + ty + i) * D_DIM + nb + tx];
    __syncthreads();
#pragma unroll
    for (int i = 0; i < 32; i += 8)
        g_Wh[((size_t)e << 20) + (size_t)(nb + ty + i) * H_DIM + kb + tx] =
            __float2half_rn(tile[tx][ty + i]);
}

// ---------------------------------------------------------------------------
// Prep: transpose + convert w1  (w1[k][n] -> [n][k], fp16)
// ---------------------------------------------------------------------------
__global__ __launch_bounds__(256) void k_tr_w1(const float* __restrict__ W) {
    __shared__ float tile[32][33];
    const int kb = blockIdx.x * 32, nb = blockIdx.y * 32;
    const int tx = threadIdx.x & 31, ty = threadIdx.x >> 5;
#pragma unroll
    for (int i = 0; i < 32; i += 8)
        tile[ty + i][tx] = W[(size_t)(kb + ty + i) * M_DIM + nb + tx];
    __syncthreads();
#pragma unroll
    for (int i = 0; i < 32; i += 8)
        g_W1h[(size_t)(nb + ty + i) * H_DIM + kb + tx] = __float2half_rn(tile[tx][ty + i]);
}

// ---------------------------------------------------------------------------
// Shared fp16 GEMM mainloop: CTA 128x128, KC=64, double-buffered cp.async,
// SW128 smem rows (128B). 8 warps = 4(m) x 2(n), warp tile 32x64.
// ---------------------------------------------------------------------------
struct Frag { float acc[2][8][4]; };

__device__ __forceinline__ void gemm_mainloop(
    uint32_t sb, int tid, const __half* aRow, const __half* bRow, Frag& fr)
{
    const int lane = tid & 31;
    const int wid = tid >> 5;
    const int warp_m = wid & 3;
    const int warp_n = wid >> 2;
    const int lr = tid >> 1;
    const int lh = tid & 1;

#pragma unroll
    for (int mi = 0; mi < 2; mi++)
#pragma unroll
        for (int ni = 0; ni < 8; ni++)
#pragma unroll
            for (int j = 0; j < 4; j++) fr.acc[mi][ni][j] = 0.f;

    auto load_chunk = [&](int c) {
        const uint32_t tb = sb + TILES_OFF + (uint32_t)(c & 1) * STAGE_B;
        const int kElem = c * 64;
#pragma unroll
        for (int j = 0; j < 4; j++) {
            const uint32_t o = SW128((uint32_t)(lr * 128 + lh * 64 + j * 16));
            CP_ASYNC16(tb + o,         (const char*)(aRow + kElem) + j * 16);
            CP_ASYNC16(tb + 16384 + o, (const char*)(bRow + kElem) + j * 16);
        }
    };

    load_chunk(0);
    CP_COMMIT();

    for (int c = 0; c < 16; c++) {
        if (c + 1 < 16) { load_chunk(c + 1); CP_COMMIT(); CP_WAIT1(); }
        else            { CP_WAIT0(); }
        __syncthreads();

        const uint32_t tb = sb + TILES_OFF + (uint32_t)(c & 1) * STAGE_B;
#pragma unroll
        for (int ks = 0; ks < 4; ks++) {
            uint32_t aF[2][4];
#pragma unroll
            for (int mi = 0; mi < 2; mi++) {
                const int row = warp_m * 32 + mi * 16 + (lane & 15);
                const uint32_t o =
                    (uint32_t)(row * 128 + ((ks * 32 + (lane >> 4) * 16) ^ ((row & 7) << 4)));
                ldsm4(aF[mi], tb + o);
            }
            uint32_t bF[8][2];
#pragma unroll
            for (int nt = 0; nt < 4; nt++) {
                const int row = warp_n * 64 + nt * 16 + ((lane >> 4) << 3) + (lane & 7);
                const uint32_t o =
                    (uint32_t)(row * 128 +
                               ((ks * 32 + ((lane >> 3) & 1) * 16) ^ ((row & 7) << 4)));
                uint32_t r4[4];
                ldsm4(r4, tb + 16384 + o);
                bF[nt * 2][0] = r4[0]; bF[nt * 2][1] = r4[1];
                bF[nt * 2 + 1][0] = r4[2]; bF[nt * 2 + 1][1] = r4[3];
            }
#pragma unroll
            for (int mi = 0; mi < 2; mi++)
#pragma unroll
                for (int ni = 0; ni < 8; ni++)
                    mma_f16(fr.acc[mi][ni], aF[mi], bF[ni]);
        }
        __syncthreads();
    }
}

// ---------------------------------------------------------------------------
// K1: fused router: h = relu(Xh @ W1h^T + b1) in regs; partial scores
//     ps = h_slice @ w2_slice written deterministically to g_part.
//     col slice id = blockIdx.y*2 + warp_n  (64 M-cols each, 8 slices total)
// ---------------------------------------------------------------------------
__global__ __launch_bounds__(256) void k_gemm1_f16(const float* __restrict__ b1,
                                                   const float* __restrict__ w2) {
    extern __shared__ char smem[];
    const uint32_t sb = smem_to_u32(smem);
    const int tid = threadIdx.x;
    const int lane = tid & 31;
    const int wid = tid >> 5;
    const int warp_m = wid & 3;
    const int warp_n = wid >> 2;
    const int rowBase = blockIdx.x * 128;
    const int colBase = blockIdx.y * 128;

    float* s_bias = (float*)(smem + 576);
    if (tid < 128) s_bias[tid] = b1[colBase + tid];
    __syncthreads();

    const int lr = tid >> 1;
    const int lh = tid & 1;
    const __half* aRow = g_Xh + (size_t)(rowBase + lr) * H_DIM + lh * 32;
    const __half* bRow = g_W1h + (size_t)(colBase + lr) * H_DIM + lh * 32;

    Frag fr;
    gemm_mainloop(sb, tid, aRow, bRow, fr);

    // load w2 slice for these 128 M-cols into (now dead) tile smem
    float* s_w2 = (float*)(smem + TILES_OFF);
    for (int i = tid; i < 128 * E_NUM; i += 256) s_w2[i] = w2[colBase * E_NUM + i];
    __syncthreads();

    // partial scores: rows r0..r3 of this thread (within CTA tile)
    float ps[4][E_NUM];
#pragma unroll
    for (int r = 0; r < 4; r++)
#pragma unroll
        for (int e = 0; e < E_NUM; e++) ps[r][e] = 0.f;

#pragma unroll
    for (int mi = 0; mi < 2; mi++) {
#pragma unroll
        for (int ni = 0; ni < 8; ni++) {
            const int col = warp_n * 64 + ni * 8 + (lane & 3) * 2;
            float v00 = fr.acc[mi][ni][0] + s_bias[col];
            float v01 = fr.acc[mi][ni][1] + s_bias[col + 1];
            float v10 = fr.acc[mi][ni][2] + s_bias[col];
            float v11 = fr.acc[mi][ni][3] + s_bias[col + 1];
            v00 = v00 > 0.f ? v00 : 0.f;  v01 = v01 > 0.f ? v01 : 0.f;
            v10 = v10 > 0.f ? v10 : 0.f;  v11 = v11 > 0.f ? v11 : 0.f;
            const float* w2a = s_w2 + col * E_NUM;
            const float* w2b = s_w2 + (col + 1) * E_NUM;
#pragma unroll
            for (int e = 0; e < E_NUM; e++) {
                ps[mi * 2 + 0][e] += v00 * w2a[e] + v01 * w2b[e];
                ps[mi * 2 + 1][e] += v10 * w2a[e] + v11 * w2b[e];
            }
        }
    }
    // reduce over the 4-lane col group -> sum over this warp's 64 cols
#pragma unroll
    for (int r = 0; r < 4; r++)
#pragma unroll
        for (int e = 0; e < E_NUM; e++) {
            float v = ps[r][e];
            v += __shfl_down_sync(0xffffffffu, v, 2, 4);
            v += __shfl_down_sync(0xffffffffu, v, 1, 4);
            ps[r][e] = v;
        }
    if ((lane & 3) == 0) {
        const int slice = blockIdx.y * 2 + warp_n;   // 0..7
        float* pbase = g_part + (size_t)slice * T_TOKENS * E_NUM;
#pragma unroll
        for (int r = 0; r < 4; r++) {
            const int mi = r >> 1, half = r & 1;
            const int token = rowBase + warp_m * 32 + mi * 16 + (lane >> 2) + half * 8;
            float* p = pbase + (size_t)token * E_NUM;
#pragma unroll
            for (int e = 0; e < E_NUM; e += 4)
                *(float4*)(p + e) = float4{ps[r][e], ps[r][e + 1], ps[r][e + 2], ps[r][e + 3]};
        }
    }
}

// ---------------------------------------------------------------------------
// K2: sum 8 slices (fixed order, deterministic) + b2 -> argmax + flag
// ---------------------------------------------------------------------------
__global__ __launch_bounds__(256) void k_argmax(const float* __restrict__ b2) {
    const int t = blockIdx.x * 256 + threadIdx.x;
    float s[E_NUM] = {b2[0], b2[1], b2[2], b2[3], b2[4], b2[5], b2[6], b2[7]};
#pragma unroll
    for (int sl = 0; sl < 8; sl++) {
        const float* p = g_part + ((size_t)sl * T_TOKENS + t) * E_NUM;
        float4 a = *(const float4*)p;
        float4 b = *(const float4*)(p + 4);
        s[0] += a.x; s[1] += a.y; s[2] += a.z; s[3] += a.w;
        s[4] += b.x; s[5] += b.y; s[6] += b.z; s[7] += b.w;
    }
    float best = s[0], second = -1e30f;
    int bi = 0;
#pragma unroll
    for (int e = 1; e < E_NUM; e++) {
        if (s[e] > best) { second = best; best = s[e]; bi = e; }
        else if (s[e] > second) { second = s[e]; }
    }
    g_top[t] = bi;
    atomicAdd(&g_counts[bi], 1);
    if (best - second < 8e-3f) {
        const int pos = atomicAdd(&g_nflag, 1);
        if (pos < FLAG_CAP) g_flag[pos] = t;
    }
}

// ---------------------------------------------------------------------------
// K2b: exact fp32 recompute for flagged tokens (deterministic), patch routing
// ---------------------------------------------------------------------------
__global__ __launch_bounds__(256) void k_fix(const float* __restrict__ X,
                                             const float* __restrict__ w1,
                                             const float* __restrict__ b1,
                                             const float* __restrict__ w2,
                                             const float* __restrict__ b2) {
    const int nf = g_nflag < FLAG_CAP ? g_nflag : FLAG_CAP;
    const int base = blockIdx.x * 4;
    if (base >= nf) return;
    const int ntok = (nf - base) < 4 ? (nf - base) : 4;

    __shared__ float x_s[4][H_DIM];
    __shared__ float h_s[4][M_DIM];
    __shared__ float ss[4][E_NUM];
    const int tid = threadIdx.x;

    for (int t = 0; t < ntok; t++) {
        const float* x = X + (size_t)g_flag[base + t] * H_DIM;
        for (int k = tid; k < H_DIM; k += 256) x_s[t][k] = x[k];
    }
    __syncthreads();

    float acc[2][4] = {};
    for (int k = 0; k < H_DIM; k++) {
        const float w0 = w1[(size_t)k * M_DIM + tid];
        const float w1v = w1[(size_t)k * M_DIM + tid + 256];
#pragma unroll
        for (int t = 0; t < 4; t++) {
            const float xv = x_s[t][k];
            acc[0][t] += w0 * xv;
            acc[1][t] += w1v * xv;
        }
    }
#pragma unroll
    for (int i = 0; i < 2; i++) {
        const int m = tid + i * 256;
        const float bb = b1[m];
#pragma unroll
        for (int t = 0; t < 4; t++) {
            const float v = acc[i][t] + bb;
            h_s[t][m] = v > 0.f ? v : 0.f;
        }
    }
    __syncthreads();

    if (tid < 4 * E_NUM) {
        const int t = tid >> 3, e = tid & 7;
        float s = 0.f;
        for (int m = 0; m < M_DIM; m++) s += h_s[t][m] * w2[m * E_NUM + e];
        ss[t][e] = s + b2[e];
    }
    __syncthreads();

    if (tid < 4 && tid < ntok) {
        float best = ss[tid][0];
        int bi = 0;
#pragma unroll
        for (int e = 1; e < E_NUM; e++)
            if (ss[tid][e] > best) { best = ss[tid][e]; bi = e; }
        const int tok = g_flag[base + tid];
        const int old = g_top[tok];
        if (bi != old) {
            g_top[tok] = bi;
            atomicSub(&g_counts[old], 1);
            atomicAdd(&g_counts[bi], 1);
        }
    }
}

__global__ void k_scan() {
    if (threadIdx.x == 0) {
        int off = 0;
        for (int e = 0; e < E_NUM; e++) {
            g_offsets[e] = off;
            g_cursor[e]  = off;
            off += g_counts[e];
        }
        g_offsets[E_NUM] = off;
    }
}

__global__ void k_scatter() {
    const int t = blockIdx.x * blockDim.x + threadIdx.x;
    if (t < T_TOKENS) {
        const int e = g_top[t];
        const int pos = atomicAdd(&g_cursor[e], 1);
        g_perm[pos] = t;
    }
}

// ---------------------------------------------------------------------------
// K5: expert GEMM (fp16 HMMA, gathered token rows)
// ---------------------------------------------------------------------------
__global__ __launch_bounds__(256) void k_expert_f16(float* __restrict__ out,
                                                    const float* __restrict__ eb) {
    const int e = blockIdx.z;
    const int off = g_offsets[e];
    const int n = g_offsets[e + 1] - off;
    const int rowBase = blockIdx.x * 128;
    if (rowBase >= n) return;

    extern __shared__ char smem[];
    const uint32_t sb = smem_to_u32(smem);
    const int tid = threadIdx.x;
    const int lane = tid & 31;
    const int wid = tid >> 5;
    const int warp_m = wid & 3;
    const int warp_n = wid >> 2;
    const int colBase = blockIdx.y * 128;

    int*   s_tok  = (int*)(smem + 64);
    float* s_bias = (float*)(smem + 576);
    if (tid < 128) {
        const int m = rowBase + tid;
        s_tok[tid]  = g_perm[off + (m < n ? m : 0)];
        s_bias[tid] = eb[(size_t)e * D_DIM + colBase + tid];
    }
    __syncthreads();

    const int lr = tid >> 1;
    const int lh = tid & 1;
    const __half* aRow = g_Xh + (size_t)s_tok[lr] * H_DIM + lh * 32;
    const __half* bRow = g_Wh + ((size_t)e << 20) + (size_t)(colBase + lr) * H_DIM + lh * 32;

    Frag fr;
    gemm_mainloop(sb, tid, aRow, bRow, fr);

#pragma unroll
    for (int mi = 0; mi < 2; mi++) {
        const int r0 = warp_m * 32 + mi * 16 + (lane >> 2);
        const int r1 = r0 + 8;
        const bool v0 = (rowBase + r0) < n;
        const bool v1 = (rowBase + r1) < n;
        float* o0 = out + (size_t)s_tok[r0] * D_DIM + colBase;
        float* o1 = out + (size_t)s_tok[r1] * D_DIM + colBase;
#pragma unroll
        for (int ni = 0; ni < 8; ni++) {
            const int col = warp_n * 64 + ni * 8 + (lane & 3) * 2;
            if (v0) {
                float2 w{fr.acc[mi][ni][0] + s_bias[col], fr.acc[mi][ni][1] + s_bias[col + 1]};
                *(float2*)(o0 + col) = w;
            }
            if (v1) {
                float2 w{fr.acc[mi][ni][2] + s_bias[col], fr.acc[mi][ni][3] + s_bias[col + 1]};
                *(float2*)(o1 + col) = w;
            }
        }
    }
}

// ---------------------------------------------------------------------------
// Launch
// ---------------------------------------------------------------------------
extern "C" void kernel_launch(void* const* d_in, const int* in_sizes, int n_in,
                              void* d_out, int out_size) {
    const float* X  = (const float*)d_in[0];
    const float* w1 = (const float*)d_in[1];
    const float* b1 = (const float*)d_in[2];
    const float* w2 = (const float*)d_in[3];
    const float* b2 = (const float*)d_in[4];
    const float* eW = (const float*)d_in[5];
    const float* eb = (const float*)d_in[6];
    float* out = (float*)d_out;

    static bool attr_set = false;
    if (!attr_set) {
        cudaFuncSetAttribute(k_expert_f16, cudaFuncAttributeMaxDynamicSharedMemorySize,
                             SMEM_BYTES);
        cudaFuncSetAttribute(k_gemm1_f16, cudaFuncAttributeMaxDynamicSharedMemorySize,
                             SMEM_BYTES);
        attr_set = true;
    }

    k_zero<<<1, 32>>>();
    k_cvt_x<<<(T_TOKENS * H_DIM) / (256 * 4), 256>>>(X);
    k_tr_w1<<<dim3(H_DIM / 32, M_DIM / 32), 256>>>(w1);
    k_tr_we<<<dim3(H_DIM / 32, D_DIM / 32, E_NUM), 256>>>(eW);
    k_gemm1_f16<<<dim3(T_TOKENS / 128, M_DIM / 128), 256, SMEM_BYTES>>>(b1, w2);
    k_argmax<<<T_TOKENS / 256, 256>>>(b2);
    k_fix<<<FLAG_CAP / 4, 256>>>(X, w1, b1, w2, b2);
    k_scan<<<1, 1>>>();
    k_scatter<<<T_TOKENS / 256, 256>>>();
    k_expert_f16<<<dim3(T_TOKENS / 128, D_DIM / 128, E_NUM), 256, SMEM_BYTES>>>(out, eb);
}